// round 2
// baseline (speedup 1.0000x reference)
#include <cuda_runtime.h>

// CharRNN: B=512, T=2048, VOCAB=96, EMBED=32, HIDDEN=128
// R2: weights in REGISTERS (64 floats/thread, k-split s=2), 512 threads/CTA.
//  - cell threads (tid<256): (j, s) hold Wh[j][s*64 +: 64]
//  - decoder threads (tid>=256): (v, s) hold Wdec[v][s*64 +: 64]  (v<96)
//  - h double-buffered in smem as float4[k] = (r0,r1,r2,r3); one broadcast
//    LDS.128 per k feeds two fma.rn.f32x2.
//  - s-partials merged via shfl.xor(1); Etab/bias added post-reduction.
//  - decoder lags cell by one step -> ONE __syncthreads per step.

#define VOCABN 96
#define EMBEDN 32
#define HID    128
#define BATCH  512
#define TLEN   2048
#define BROWS  4
#define NBLK   (BATCH / BROWS)   // 128
#define NTHR   512

typedef unsigned long long u64;

__device__ __forceinline__ u64 ffma2(u64 a, u64 b, u64 c) {
    u64 d;
    asm("fma.rn.f32x2 %0, %1, %2, %3;" : "=l"(d) : "l"(a), "l"(b), "l"(c));
    return d;
}
__device__ __forceinline__ u64 fadd2(u64 a, u64 b) {
    u64 d;
    asm("add.rn.f32x2 %0, %1, %2;" : "=l"(d) : "l"(a), "l"(b));
    return d;
}
__device__ __forceinline__ u64 pack2(float x, float y) {
    u64 d;
    asm("mov.b64 %0, {%1, %2};" : "=l"(d) : "f"(x), "f"(y));
    return d;
}
__device__ __forceinline__ float2 unpack2(u64 a) {
    float2 r;
    asm("mov.b64 {%0, %1}, %2;" : "=f"(r.x), "=f"(r.y) : "l"(a));
    return r;
}

union F4U { float4 f4; u64 u[2]; };

// SMEM (floats):
//  Et   : 96*128  = 12288  [v*128 + j]  (e@We^T + b_cell lookup table)
//  hbuf : 2*128*4 = 1024   float4 per k: (r0,r1,r2,r3), double buffered
//  xs   : 4*2048  = 8192   ints, [t*4 + r]
#define OFF_ET  0
#define OFF_H   (OFF_ET + VOCABN*HID)
#define OFF_X   (OFF_H + 2*HID*4)
#define SMEM_FLOATS (OFF_X + BROWS*TLEN)
#define SMEM_BYTES  (SMEM_FLOATS * 4)

__global__ void __launch_bounds__(NTHR, 1)
charrnn_kernel(const int* __restrict__ x,
               const float* __restrict__ h0,
               const float* __restrict__ emb,
               const float* __restrict__ Wcell,   // [128][160]
               const float* __restrict__ bcell,   // [128]
               const float* __restrict__ Wdec,    // [96][128]
               const float* __restrict__ bdec,    // [96]
               float* __restrict__ out,           // [512][2048][96]
               float* __restrict__ hfin)          // [512][128] or null
{
    extern __shared__ float smem[];
    float*  Et   = smem + OFF_ET;
    float4* hbuf = (float4*)(smem + OFF_H);
    int*    xs   = (int*)(smem + OFF_X);

    const int tid = threadIdx.x;
    const int b0  = blockIdx.x * BROWS;
    const bool isCell = (tid < 256);
    const int lj = (tid & 255) >> 1;   // cell: j;  decoder: v
    const int s  = tid & 1;            // k-half
    const int j  = lj;                 // cell hidden index
    const int v  = lj;                 // decoder vocab index (active if <96)
    const bool decActive = (!isCell) && (v < VOCABN);

    // -------- one-time init --------
    float w[64];
    float bv = 0.f;
    if (isCell) {
        #pragma unroll
        for (int k = 0; k < 64; k++)
            w[k] = Wcell[j * (EMBEDN + HID) + EMBEDN + s * 64 + k];
    } else if (decActive) {
        #pragma unroll
        for (int k = 0; k < 64; k++)
            w[k] = Wdec[v * HID + s * 64 + k];
        bv = bdec[v];
    }

    // Etab: Et[vv*128 + jj] = b_cell[jj] + sum_k emb[vv][k]*We[jj][k]
    if (tid < HID) {
        const int jj = tid;
        float we[EMBEDN];
        #pragma unroll
        for (int k = 0; k < EMBEDN; k++)
            we[k] = Wcell[jj * (EMBEDN + HID) + k];
        const float bc = bcell[jj];
        for (int vv = 0; vv < VOCABN; vv++) {
            float a = bc;
            #pragma unroll
            for (int k = 0; k < EMBEDN; k++)
                a = fmaf(emb[vv * EMBEDN + k], we[k], a);
            Et[vv * HID + jj] = a;
        }
    }

    // token prefetch: xs[t*4 + r] = x[(b0+r)*T + t]
    for (int i = tid; i < BROWS * TLEN; i += NTHR) {
        int t = i >> 2, r = i & 3;
        xs[i] = x[(b0 + r) * TLEN + t];
    }

    // h0 -> buf0: thread (j,s) writes rows (2s, 2s+1)
    if (isCell) {
        float2 h2 = make_float2(h0[(b0 + 2 * s + 0) * HID + j],
                                h0[(b0 + 2 * s + 1) * HID + j]);
        ((float2*)hbuf)[j * 2 + s] = h2;
    }
    __syncthreads();

    float th0 = 0.f, th1 = 0.f;   // cell: last tanh'd rows (2s, 2s+1)
    const size_t RS = (size_t)TLEN * VOCABN;

    // -------- main loop --------
    #pragma unroll 1
    for (int t = 0; t < TLEN; t++) {
        const float4* hpp = hbuf + (t & 1) * HID + s * 64;  // this thread's k-slice

        if (isCell) {
            u64 aA01 = 0ull, aB01 = 0ull, aA23 = 0ull, aB23 = 0ull;
            #pragma unroll
            for (int k = 0; k < 64; k += 2) {
                F4U hv0; hv0.f4 = hpp[k];
                u64 wp0 = pack2(w[k], w[k]);
                aA01 = ffma2(hv0.u[0], wp0, aA01);
                aA23 = ffma2(hv0.u[1], wp0, aA23);
                F4U hv1; hv1.f4 = hpp[k + 1];
                u64 wp1 = pack2(w[k + 1], w[k + 1]);
                aB01 = ffma2(hv1.u[0], wp1, aB01);
                aB23 = ffma2(hv1.u[1], wp1, aB23);
            }
            u64 a01 = fadd2(aA01, aB01);
            u64 a23 = fadd2(aA23, aB23);
            float2 p01 = unpack2(a01), p23 = unpack2(a23);
            // merge s-halves: after this every thread has all 4 full sums
            float f0 = p01.x + __shfl_xor_sync(0xffffffffu, p01.x, 1);
            float f1 = p01.y + __shfl_xor_sync(0xffffffffu, p01.y, 1);
            float f2 = p23.x + __shfl_xor_sync(0xffffffffu, p23.x, 1);
            float f3 = p23.y + __shfl_xor_sync(0xffffffffu, p23.y, 1);
            // this thread finalizes rows (2s, 2s+1)
            float u0 = s ? f2 : f0;
            float u1 = s ? f3 : f1;
            const int4 iv = ((const int4*)xs)[t];
            const int i0 = s ? iv.z : iv.x;
            const int i1 = s ? iv.w : iv.y;
            u0 += Et[i0 * HID + j];
            u1 += Et[i1 * HID + j];
            th0 = tanhf(u0);
            th1 = tanhf(u1);
            ((float2*)(hbuf + ((t + 1) & 1) * HID))[j * 2 + s] = make_float2(th0, th1);
        } else if (decActive && t > 0) {
            // out[t-1] from h_t (= buf[t&1])
            u64 aA01 = 0ull, aB01 = 0ull, aA23 = 0ull, aB23 = 0ull;
            #pragma unroll
            for (int k = 0; k < 64; k += 2) {
                F4U hv0; hv0.f4 = hpp[k];
                u64 wp0 = pack2(w[k], w[k]);
                aA01 = ffma2(hv0.u[0], wp0, aA01);
                aA23 = ffma2(hv0.u[1], wp0, aA23);
                F4U hv1; hv1.f4 = hpp[k + 1];
                u64 wp1 = pack2(w[k + 1], w[k + 1]);
                aB01 = ffma2(hv1.u[0], wp1, aB01);
                aB23 = ffma2(hv1.u[1], wp1, aB23);
            }
            u64 a01 = fadd2(aA01, aB01);
            u64 a23 = fadd2(aA23, aB23);
            float2 p01 = unpack2(a01), p23 = unpack2(a23);
            float f0 = p01.x + __shfl_xor_sync(0xffffffffu, p01.x, 1);
            float f1 = p01.y + __shfl_xor_sync(0xffffffffu, p01.y, 1);
            float f2 = p23.x + __shfl_xor_sync(0xffffffffu, p23.x, 1);
            float f3 = p23.y + __shfl_xor_sync(0xffffffffu, p23.y, 1);
            float g0 = (s ? f2 : f0) + bv;   // row 2s
            float g1 = (s ? f3 : f1) + bv;   // row 2s+1
            const size_t ob = (size_t)(t - 1) * VOCABN + v;
            out[(size_t)(b0 + 2 * s + 0) * RS + ob] = g0;
            out[(size_t)(b0 + 2 * s + 1) * RS + ob] = g1;
        }
        __syncthreads();
    }

    // -------- epilogue --------
    if (isCell) {
        if (hfin) {
            hfin[(b0 + 2 * s + 0) * HID + j] = th0;
            hfin[(b0 + 2 * s + 1) * HID + j] = th1;
        }
    } else if (decActive) {
        // out[T-1] from h_T (= buf[T&1] = buf0)
        const float4* hpp = hbuf + (TLEN & 1) * HID + s * 64;
        u64 aA01 = 0ull, aB01 = 0ull, aA23 = 0ull, aB23 = 0ull;
        #pragma unroll
        for (int k = 0; k < 64; k += 2) {
            F4U hv0; hv0.f4 = hpp[k];
            u64 wp0 = pack2(w[k], w[k]);
            aA01 = ffma2(hv0.u[0], wp0, aA01);
            aA23 = ffma2(hv0.u[1], wp0, aA23);
            F4U hv1; hv1.f4 = hpp[k + 1];
            u64 wp1 = pack2(w[k + 1], w[k + 1]);
            aB01 = ffma2(hv1.u[0], wp1, aB01);
            aB23 = ffma2(hv1.u[1], wp1, aB23);
        }
        u64 a01 = fadd2(aA01, aB01);
        u64 a23 = fadd2(aA23, aB23);
        float2 p01 = unpack2(a01), p23 = unpack2(a23);
        float f0 = p01.x + __shfl_xor_sync(0xffffffffu, p01.x, 1);
        float f1 = p01.y + __shfl_xor_sync(0xffffffffu, p01.y, 1);
        float f2 = p23.x + __shfl_xor_sync(0xffffffffu, p23.x, 1);
        float f3 = p23.y + __shfl_xor_sync(0xffffffffu, p23.y, 1);
        float g0 = (s ? f2 : f0) + bv;
        float g1 = (s ? f3 : f1) + bv;
        const size_t ob = (size_t)(TLEN - 1) * VOCABN + v;
        out[(size_t)(b0 + 2 * s + 0) * RS + ob] = g0;
        out[(size_t)(b0 + 2 * s + 1) * RS + ob] = g1;
    }
}

extern "C" void kernel_launch(void* const* d_in, const int* in_sizes, int n_in,
                              void* d_out, int out_size)
{
    const int*   x     = (const int*)d_in[0];
    const float* h0    = (const float*)d_in[1];
    const float* emb   = (const float*)d_in[2];
    const float* Wcell = (const float*)d_in[3];
    const float* bcell = (const float*)d_in[4];
    const float* Wdec  = (const float*)d_in[5];
    const float* bdec  = (const float*)d_in[6];

    float* out = (float*)d_out;
    const long long outs_elems = (long long)BATCH * TLEN * VOCABN;
    float* hfin = nullptr;
    if ((long long)out_size >= outs_elems + (long long)BATCH * HID)
        hfin = out + outs_elems;

    cudaFuncSetAttribute(charrnn_kernel,
                         cudaFuncAttributeMaxDynamicSharedMemorySize, SMEM_BYTES);

    charrnn_kernel<<<NBLK, NTHR, SMEM_BYTES>>>(x, h0, emb, Wcell, bcell,
                                               Wdec, bdec, out, hfin);
}